// round 8
// baseline (speedup 1.0000x reference)
#include <cuda_runtime.h>

#define N_CELLS 776
#define N_ANCHORS 3
#define N_CH 7
#define CONF_THRESH 0.8f
#define NO_OBJECT 0.5f

#define NTH 512
#define N_FLOATS (N_CELLS * N_ANCHORS * N_CH)   // 16296
#define N_F4 (N_FLOATS / 4)                     // 4074
#define SMEM_BYTES (N_FLOATS * sizeof(float))   // 65184

__global__ __launch_bounds__(NTH, 1)
void yolo_loss_kernel(const float* __restrict__ pred,
                      const float* __restrict__ label,
                      float* __restrict__ out)
{
    extern __shared__ float s[];                // staged pred, 16296 floats
    __shared__ float warp_sums[NTH / 32];

    const int tid = threadIdx.x;

    // ---- Phase 1: coalesced staging GMEM -> SMEM (float4) ----
    const float4* p4 = (const float4*)pred;
    float4* s4 = (float4*)s;
    #pragma unroll
    for (int i = tid; i < N_F4; i += NTH)
        s4[i] = p4[i];

    // label broadcast loads (independent of staging; overlap latency)
    const float lx = __ldg(&label[0]);
    const float ly = __ldg(&label[1]);
    const float lw = __ldg(&label[2]);
    const float lh = __ldg(&label[3]);
    const float lconf = __ldg(&label[4]);
    const float lc5 = __ldg(&label[5]);
    const float lc6 = __ldg(&label[6]);

    const float area_b = fabsf(lw * lh);
    const float lxm = lx - lw * 0.5f, lym = ly - lh * 0.5f;
    const float lxp = lx + lw * 0.5f, lyp = ly + lh * 0.5f;
    const float slx = sqrtf(lx), sly = sqrtf(ly);

    __syncthreads();

    // ---- Phase 2: per-cell loss from SMEM (conflict-free: stride 21 is odd) ----
    float loss = 0.0f;
    for (int c = tid; c < N_CELLS; c += NTH) {
        const int row = c * (N_ANCHORS * N_CH);

        float best_iou = -1.0f;
        int best_a = 0;
        float bpx = 0.0f, bpy = 0.0f;
        #pragma unroll
        for (int a = 0; a < N_ANCHORS; a++) {
            const float px = s[row + a * N_CH + 0];
            const float py = s[row + a * N_CH + 1];
            const float pw = s[row + a * N_CH + 2];
            const float ph = s[row + a * N_CH + 3];
            const float ax = fmaxf(px - pw * 0.5f, lxm);
            const float ay = fmaxf(py - ph * 0.5f, lym);
            const float bx = fminf(px + pw * 0.5f, lxp);
            const float by = fminf(py + ph * 0.5f, lyp);
            const float inter = fabsf(fmaxf(bx - ax, 0.0f) * fmaxf(by - ay, 0.0f));
            const float area_a = fabsf(pw * ph);
            const float iou = inter / (area_a + area_b - inter);
            if (iou > best_iou) { best_iou = iou; best_a = a; bpx = px; bpy = py; }
        }

        const int base = row + best_a * N_CH;
        const float b4 = s[base + 4];
        const float b5 = s[base + 5];
        const float b6 = s[base + 6];

        const float dx = lx - bpx, dy = ly - bpy;
        const float xy_loss = dx * dx + dy * dy;
        const float sdx = slx - sqrtf(bpx);
        const float sdy = sly - sqrtf(bpy);
        const float wh_loss = sdx * sdx + sdy * sdy;

        const bool has_obj = b4 > CONF_THRESH;
        float class_loss = 0.0f;
        if (has_obj) {
            const float d5 = lc5 - b5, d6 = lc6 - b6;
            class_loss = d5 * d5 + d6 * d6;
        }
        const float dc = lconf - b4;
        const float conf_sq = dc * dc;
        const float conf_loss = has_obj ? conf_sq : NO_OBJECT * conf_sq;

        loss += xy_loss + wh_loss + class_loss + conf_loss;
    }

    // ---- Phase 3: deterministic reduction (warp shuffle + one barrier) ----
    #pragma unroll
    for (int off = 16; off > 0; off >>= 1)
        loss += __shfl_down_sync(0xFFFFFFFF, loss, off);
    if ((tid & 31) == 0) warp_sums[tid >> 5] = loss;
    __syncthreads();

    if (tid < 32) {
        float v = (tid < NTH / 32) ? warp_sums[tid] : 0.0f;
        #pragma unroll
        for (int off = 8; off > 0; off >>= 1)
            v += __shfl_down_sync(0xFFFFFFFF, v, off);
        if (tid == 0) out[0] = v;
    }
}

extern "C" void kernel_launch(void* const* d_in, const int* in_sizes, int n_in,
                              void* d_out, int out_size)
{
    const float* pred  = (const float*)d_in[0];
    const float* label = (const float*)d_in[1];
    float* out = (float*)d_out;

    static bool attr_set = false;
    if (!attr_set) {
        cudaFuncSetAttribute(yolo_loss_kernel,
                             cudaFuncAttributeMaxDynamicSharedMemorySize,
                             SMEM_BYTES);
        attr_set = true;
    }
    yolo_loss_kernel<<<1, NTH, SMEM_BYTES>>>(pred, label, out);
}